// round 4
// baseline (speedup 1.0000x reference)
#include <cuda_runtime.h>
#include <math.h>

#define NH   200
#define BR   8
#define HB   4      // branches per half-thread
#define IND  120
#define OD   35
#define TT   250
#define PER  15
#define BPC  4      // batches per CTA
#define W2S  201    // padded W2 row stride
#define NTHR 512

typedef unsigned long long u64;

__device__ __forceinline__ u64 pk2(float lo, float hi) {
    u64 r; asm("mov.b64 %0,{%1,%2};" : "=l"(r) : "f"(lo), "f"(hi)); return r;
}
__device__ __forceinline__ void upk2(u64 v, float& lo, float& hi) {
    asm("mov.b64 {%0,%1},%2;" : "=f"(lo), "=f"(hi) : "l"(v));
}
__device__ __forceinline__ u64 fma2(u64 a, u64 b, u64 c) {
    u64 d; asm("fma.rn.f32x2 %0,%1,%2,%3;" : "=l"(d) : "l"(a), "l"(b), "l"(c)); return d;
}
__device__ __forceinline__ u64 mul2(u64 a, u64 b) {
    u64 d; asm("mul.rn.f32x2 %0,%1,%2;" : "=l"(d) : "l"(a), "l"(b)); return d;
}
__device__ __forceinline__ u64 add2(u64 a, u64 b) {
    u64 d; asm("add.rn.f32x2 %0,%1,%2;" : "=l"(d) : "l"(a), "l"(b)); return d;
}
__device__ __forceinline__ float sigm(float v) { return 1.0f / (1.0f + expf(-v)); }

// ---- dynamic smem layout (byte offsets, all 16B aligned) ----
#define OFF_XS   0                       // float xs[2][BPC][128]          = 4096
#define OFF_LP   4096                    // u64 lp[2][2][2][NH]            = 12800
#define OFF_SPK  (OFF_LP + 12800)        // u64 spk[2][2][NH]              = 6400
#define OFF_PS   (OFF_SPK + 6400)        // u64 ps[2][2][112]              = 7168
#define OFF_W2   (OFF_PS + 7168)         // float W2s[OD*W2S] = 28140 -> 28160
#define OFF_ACC  (OFF_W2 + 28160)        // float accS[BPC][OD]            = 560
#define SMEM_TOTAL (OFF_ACC + 576)       // ~59.2 KB

__global__ __launch_bounds__(NTHR, 1)
void snn512_kernel(const float* __restrict__ x,
                   const float* __restrict__ W1,
                   const float* __restrict__ b1,
                   const float* __restrict__ tau_m1,
                   const float* __restrict__ tau_n1,
                   const float* __restrict__ W2,
                   const float* __restrict__ b2,
                   const float* __restrict__ tau_m2,
                   float* __restrict__ out)
{
    extern __shared__ __align__(16) char smem[];
    float (*xs)[BPC][128]   = (float (*)[BPC][128])(smem + OFF_XS);
    u64   (*lp)[2][2][NH]   = (u64 (*)[2][2][NH])(smem + OFF_LP);   // [buf][pair][half][n]
    u64   (*spk)[2][NH]     = (u64 (*)[2][NH])(smem + OFF_SPK);     // [buf][pair][n]
    u64   (*ps)[2][112]     = (u64 (*)[2][112])(smem + OFF_PS);     // [buf][pair][slot]
    float *W2s              = (float*)(smem + OFF_W2);
    float (*accS)[OD]       = (float (*)[OD])(smem + OFF_ACC);

    const int tid = threadIdx.x;
    const int b0  = blockIdx.x * BPC;

    // ---- roles ----
    const bool isDen = (tid < 2 * NH);               // threads 0..399
    const int  h     = (tid >= NH) ? 1 : 0;          // branch half
    const int  dn    = tid - NH * h;                 // neuron
    const int  rr    = tid - 400;                    // readout slot
    const bool doRO  = (rr >= 0 && rr < 3 * OD);     // threads 400..504
    const int  ss    = doRO ? (rr / OD) : 0;
    const int  oo    = doRO ? (rr - ss * OD) : 0;
    const int  rn0   = ss * 67;
    const int  rn1   = (rn0 + 67 < NH) ? (rn0 + 67) : NH;
    const bool doRED = (rr >= 0 && rr < OD);         // threads 400..434

    // ---- W2 -> smem (padded rows) ----
    for (int i = tid; i < OD * NH; i += NTHR) {
        int o = i / NH, n = i - o * NH;
        W2s[o * W2S + n] = W2[i];
    }
    // zero slot-15 pads: 2 bufs x 4 batches x 8 branches
    if (tid < 64) {
        int buf = tid >> 5, rest = tid & 31, bj = rest >> 3, k = rest & 7;
        xs[buf][bj][k * 16 + 15] = 0.0f;
    }

    // ---- dendrite weights: 4 branches, (1-beta) folded, slot-pair packed ----
    u64   w2r[HB * 8];
    float beta[HB], dst[BPC][HB];
    float bb05 = 0.0f;                    // b1/2, folded into each half's partial
    if (isDen) {
        #pragma unroll
        for (int kk = 0; kk < HB; kk++) {
            const int k = h * HB + kk;
            float bt = sigm(tau_n1[dn * BR + k]);
            beta[kk] = bt;
            float sc = 1.0f - bt;
            const float* src = W1 + (size_t)dn * (BR * IND) + k * IND + k * PER;
            float wr[16];
            #pragma unroll
            for (int j = 0; j < PER; j++) wr[j] = src[j] * sc;
            wr[15] = 0.0f;
            #pragma unroll
            for (int m = 0; m < 8; m++) w2r[kk * 8 + m] = pk2(wr[2 * m], wr[2 * m + 1]);
        }
        bb05 = 0.5f * b1[dn];
    }
    #pragma unroll
    for (int bj = 0; bj < BPC; bj++)
        #pragma unroll
        for (int kk = 0; kk < HB; kk++) dst[bj][kk] = 0.0f;

    // ---- soma state (threads 0..199 own neuron tid) ----
    float a1 = 0.f, oma1 = 0.f, mem1[BPC], spkv[BPC];
    #pragma unroll
    for (int bj = 0; bj < BPC; bj++) { mem1[bj] = 0.f; spkv[bj] = 0.f; }
    if (tid < NH) { a1 = sigm(tau_m1[tid]); oma1 = 1.0f - a1; }

    // ---- integrator state (threads 400..434 own output rr) ----
    float a2 = 0.f, bb2 = 0.f, mem2[BPC], racc[BPC];
    #pragma unroll
    for (int bj = 0; bj < BPC; bj++) { mem2[bj] = 0.f; racc[bj] = 0.f; }
    if (doRED) { a2 = sigm(tau_m2[rr]); bb2 = b2[rr]; }

    // ---- x loader: thread i<480 loads one (batch, feature) per step ----
    const float* xptr = nullptr;
    int lbj = 0, xoff = 0;
    if (tid < 480) {
        lbj = tid / IND;
        int f = tid - lbj * IND;
        int c = f / 40, dd = f - c * 40;
        xptr = x + ((size_t)((b0 + lbj) * 3 + c) * TT) * 40 + dd;
        xoff = (f / PER) * 16 + (f % PER);
    }

    // prologue: x_0 -> buffer 0
    if (tid < 480) xs[0][lbj][xoff] = xptr[0];
    __syncthreads();

    // ======== main loop: 4-stage pipeline, 1 barrier/iteration ========
    for (int t = 0; t < TT + 3; t++) {
        const int cur = t & 1, prv = cur ^ 1;

        // prefetch x_{t+1}
        float xn = 0.0f;
        if (tid < 480 && t < TT - 1) xn = __ldg(xptr + (size_t)(t + 1) * 40);

        // ---- stage 1: dendrite half for step t ----
        if (t < TT && isDen) {
            const int xbase = h * (HB * 16);      // float offset of this half
            float lb[BPC];
            #pragma unroll
            for (int bj = 0; bj < BPC; bj++) {
                const ulonglong2* xv = (const ulonglong2*)&xs[cur][bj][xbase];
                float acc = bb05;
                #pragma unroll
                for (int kk = 0; kk < HB; kk++) {
                    ulonglong2 v0 = xv[kk * 4 + 0];
                    ulonglong2 v1 = xv[kk * 4 + 1];
                    ulonglong2 v2 = xv[kk * 4 + 2];
                    ulonglong2 v3 = xv[kk * 4 + 3];
                    u64 sA = mul2(v0.x, w2r[kk * 8 + 0]);
                    u64 sB = mul2(v0.y, w2r[kk * 8 + 1]);
                    sA = fma2(v1.x, w2r[kk * 8 + 2], sA);
                    sB = fma2(v1.y, w2r[kk * 8 + 3], sB);
                    sA = fma2(v2.x, w2r[kk * 8 + 4], sA);
                    sB = fma2(v2.y, w2r[kk * 8 + 5], sB);
                    sA = fma2(v3.x, w2r[kk * 8 + 6], sA);
                    sB = fma2(v3.y, w2r[kk * 8 + 7], sB);
                    u64 I2 = add2(sA, sB);
                    float il, ih; upk2(I2, il, ih);
                    float d = fmaf(beta[kk], dst[bj][kk], il + ih);
                    dst[bj][kk] = d;
                    acc += d;
                }
                lb[bj] = acc;
            }
            lp[cur][0][h][dn] = pk2(lb[0], lb[1]);
            lp[cur][1][h][dn] = pk2(lb[2], lb[3]);
        }

        // ---- stage 2: soma for step t-1 (threads 0..199) ----
        if (tid < NH && t >= 1 && t <= TT) {
            #pragma unroll
            for (int p = 0; p < 2; p++) {
                u64 s2 = add2(lp[prv][p][0][tid], lp[prv][p][1][tid]);
                float l0, l1; upk2(s2, l0, l1);
                const int i0 = 2 * p, i1 = 2 * p + 1;
                float m0 = fmaf(a1, mem1[i0] - spkv[i0], oma1 * l0);
                mem1[i0] = m0; spkv[i0] = (m0 > 1.0f) ? 1.0f : 0.0f;
                float m1 = fmaf(a1, mem1[i1] - spkv[i1], oma1 * l1);
                mem1[i1] = m1; spkv[i1] = (m1 > 1.0f) ? 1.0f : 0.0f;
                spk[cur][p][tid] = pk2(spkv[i0], spkv[i1]);
            }
        }

        // stage next x into the other buffer
        if (tid < 480 && t < TT - 1) xs[prv][lbj][xoff] = xn;

        // ---- stage 3: readout partials for step t-2 (threads 400..504) ----
        if (doRO && t >= 2 && t <= TT + 1) {
            u64 p0 = 0ULL, p1 = 0ULL;
            const float* wrow = W2s + oo * W2S;
            for (int nn = rn0; nn < rn1; nn++) {
                float wv = wrow[nn];
                u64 wd = pk2(wv, wv);
                p0 = fma2(spk[prv][0][nn], wd, p0);
                p1 = fma2(spk[prv][1][nn], wd, p1);
            }
            ps[cur][0][rr] = p0;
            ps[cur][1][rr] = p1;
        }

        // ---- stage 4: reduce + leaky integrator for step t-3 (threads 400..434) ----
        if (doRED && t >= 3) {
            #pragma unroll
            for (int p = 0; p < 2; p++) {
                u64 r2 = add2(add2(ps[prv][p][rr], ps[prv][p][OD + rr]),
                              ps[prv][p][2 * OD + rr]);
                float r0, r1; upk2(r2, r0, r1);
                const int i0 = 2 * p, i1 = 2 * p + 1;
                float t0 = r0 + bb2;
                float m0 = fmaf(a2, mem2[i0] - t0, t0);
                mem2[i0] = m0; racc[i0] += m0;
                float t1 = r1 + bb2;
                float m1 = fmaf(a2, mem2[i1] - t1, t1);
                mem2[i1] = m1; racc[i1] += m1;
            }
        }

        __syncthreads();
    }

    // ---- epilogue: log_softmax(acc/T) per batch ----
    if (doRED) {
        #pragma unroll
        for (int bj = 0; bj < BPC; bj++)
            accS[bj][rr] = racc[bj] * (1.0f / TT);
    }
    __syncthreads();
    if (tid < BPC * OD) {
        int bj = tid / OD, o = tid - bj * OD;
        float m = -INFINITY;
        #pragma unroll
        for (int i = 0; i < OD; i++) m = fmaxf(m, accS[bj][i]);
        float se = 0.0f;
        #pragma unroll
        for (int i = 0; i < OD; i++) se += expf(accS[bj][i] - m);
        out[(size_t)(b0 + bj) * OD + o] = accS[bj][o] - m - logf(se);
    }
}

extern "C" void kernel_launch(void* const* d_in, const int* in_sizes, int n_in,
                              void* d_out, int out_size)
{
    const float* x      = (const float*)d_in[0];
    const float* W1     = (const float*)d_in[1];
    const float* b1     = (const float*)d_in[2];
    const float* tau_m1 = (const float*)d_in[3];
    const float* tau_n1 = (const float*)d_in[4];
    const float* W2     = (const float*)d_in[5];
    const float* b2     = (const float*)d_in[6];
    const float* tau_m2 = (const float*)d_in[7];
    float* out = (float*)d_out;

    cudaFuncSetAttribute(snn512_kernel,
                         cudaFuncAttributeMaxDynamicSharedMemorySize, SMEM_TOTAL);

    const int B = in_sizes[0] / (3 * TT * 40);   // 512
    snn512_kernel<<<B / BPC, NTHR, SMEM_TOTAL>>>(x, W1, b1, tau_m1, tau_n1,
                                                 W2, b2, tau_m2, out);
}